// round 8
// baseline (speedup 1.0000x reference)
#include <cuda_runtime.h>
#include <cfloat>

// Problem constants (fixed by reference: B=128, N=4096, P=4096, K=100)
constexpr int RB = 128;
constexpr int RN = 4096;
constexpr int RP = 4096;
constexpr int RK = 100;
constexpr int KPAD = 128;        // padded sorted-array size (power of two)
constexpr int STH  = 256;        // stage kernel threads
constexpr int NTH  = 128;        // nn kernel threads
constexpr int PBATCH = 4;        // independent searches in flight per thread
constexpr int SPLIT  = 8;        // CTAs per row in the NN kernel
constexpr int PCHUNK = RP / SPLIT;        // 512 points per NN CTA
static_assert(PCHUNK == NTH * PBATCH, "chunk mismatch");
constexpr int NBLOCKS = RB * SPLIT;       // 1024 NN CTAs
constexpr int PRE = 512;         // prefix/suffix probe length for sign scans

// Per-row staged tables (written by stage_kernel, read by nn_kernel)
__device__ float  g_sxs[RB][KPAD];   // sorted x, padded with +inf
__device__ float  g_sdv[RB][RK];     // dvals in sorted order
__device__ int    g_sks[RB][RK];     // original k in sorted order
__device__ int    g_sfr[RB][RK];     // first index of duplicate run
__device__ double g_part_sum[RB * SPLIT];
__device__ double g_part_sq [RB * SPLIT];
__device__ unsigned int g_ticket;    // zero-initialized; reset by last block each run

// ---------------------------------------------------------------------------
// Kernel 1: per-row shift + gather + rank-sort -> tables in gmem
// ---------------------------------------------------------------------------
__global__ void __launch_bounds__(STH, 1)
stage_kernel(const float* __restrict__ preds,
             const float* __restrict__ target,
             const float* __restrict__ Xffp,
             const float* __restrict__ amp)
{
    // PDL: allow the dependent NN grid to start launching now; its reads of
    // our output are gated by cudaGridDependencySynchronize() on its side.
    cudaTriggerProgrammaticLaunchCompletion();

    const int b   = blockIdx.x;
    const int tid = threadIdx.x;
    const float* trow = target + (size_t)b * RN;

    __shared__ int   s_min[STH];
    __shared__ int   s_max[STH];
    __shared__ int   s_shift;
    __shared__ float rx[RK];       // gathered X100 (unsorted)
    __shared__ float rd[RK];       // gathered dvals (unsorted)
    __shared__ float sxs[KPAD];    // sorted x

    // ---- Phase A: sign scans over target row ----
    // normal_u = target/amp with amp in [0.5,1.5] > 0, so:
    //   normal_u >= 0  <=>  target >= 0     (j_left = first such index)
    //   normal_u <= 0  <=>  target <= 0     (m_right via last such index)
    // Probe a 512-element prefix (resp. suffix). "No hit in prefix" is exactly
    // the condition under which indices >= PRE can matter, so the rare
    // full-row fallback keeps this exact.
    int mn = RN;   // min index with target[n] >= 0
    int mx = -1;   // max index with target[n] <= 0
    {
        const float4* t4 = reinterpret_cast<const float4*>(trow);
        #pragma unroll
        for (int i = tid; i < PRE / 4; i += STH) {   // prefix probe
            float4 v = t4[i];
            int base = i * 4;
            if (v.x >= 0.f) mn = min(mn, base + 0);
            if (v.y >= 0.f) mn = min(mn, base + 1);
            if (v.z >= 0.f) mn = min(mn, base + 2);
            if (v.w >= 0.f) mn = min(mn, base + 3);
        }
        #pragma unroll
        for (int i = tid; i < PRE / 4; i += STH) {   // suffix probe
            int i4 = (RN - PRE) / 4 + i;
            float4 v = t4[i4];
            int base = i4 * 4;
            if (v.x <= 0.f) mx = max(mx, base + 0);
            if (v.y <= 0.f) mx = max(mx, base + 1);
            if (v.z <= 0.f) mx = max(mx, base + 2);
            if (v.w <= 0.f) mx = max(mx, base + 3);
        }
    }
    s_min[tid] = mn;
    s_max[tid] = mx;
    __syncthreads();
    for (int s = STH / 2; s > 0; s >>= 1) {
        if (tid < s) {
            s_min[tid] = min(s_min[tid], s_min[tid + s]);
            s_max[tid] = max(s_max[tid], s_max[tid + s]);
        }
        __syncthreads();
    }
    // Rare fallback: prefix (resp. suffix) was sign-pure -> full-row scan.
    if (s_min[0] == RN || s_max[0] == -1) {
        const bool need_mn = (s_min[0] == RN);
        const bool need_mx = (s_max[0] == -1);
        mn = RN; mx = -1;
        const float4* t4 = reinterpret_cast<const float4*>(trow);
        for (int i = tid; i < RN / 4; i += STH) {
            float4 v = t4[i];
            int base = i * 4;
            if (need_mn) {
                if (v.x >= 0.f) mn = min(mn, base + 0);
                if (v.y >= 0.f) mn = min(mn, base + 1);
                if (v.z >= 0.f) mn = min(mn, base + 2);
                if (v.w >= 0.f) mn = min(mn, base + 3);
            }
            if (need_mx) {
                if (v.x <= 0.f) mx = max(mx, base + 0);
                if (v.y <= 0.f) mx = max(mx, base + 1);
                if (v.z <= 0.f) mx = max(mx, base + 2);
                if (v.w <= 0.f) mx = max(mx, base + 3);
            }
        }
        __syncthreads();
        if (need_mn) s_min[tid] = mn;
        if (need_mx) s_max[tid] = mx;
        __syncthreads();
        for (int s = STH / 2; s > 0; s >>= 1) {
            if (tid < s) {
                if (need_mn) s_min[tid] = min(s_min[tid], s_min[tid + s]);
                if (need_mx) s_max[tid] = max(s_max[tid], s_max[tid + s]);
            }
            __syncthreads();
        }
    }
    if (tid == 0) {
        int jl = s_min[0];
        if (jl == RN) jl = 0;           // argmax of all-False -> 0
        int k_left = jl + 1;
        int mxi = s_max[0];
        int m_right = (mxi < 0) ? 0 : (RN - 1 - mxi);
        float first = trow[0];
        float last  = trow[RN - 1];
        bool left_case = (last < 0.f) && (first < 0.f);
        s_shift = left_case ? -k_left : m_right;
    }
    __syncthreads();

    // ---- Phase B: gather first K shifted elements, stable rank-sort ----
    if (tid < RK) {
        int i = tid - s_shift;
        i %= RN;
        if (i < 0) i += RN;
        size_t g = (size_t)b * RN + i;
        float a = amp[g];
        rx[tid] = Xffp[g];
        rd[tid] = target[g] / a - preds[g] / a;   // nu_s - nui_s, literal order
    }
    __syncthreads();
    if (tid < RK) {
        float x = rx[tid];
        int rank = 0;
        #pragma unroll 4
        for (int j = 0; j < RK; j++) {
            float xj = rx[j];
            rank += (xj < x) || (xj == x && j < tid);  // stable: ties by original index
        }
        sxs[rank] = x;
        g_sxs[b][rank] = x;
        g_sdv[b][rank] = rd[tid];
        g_sks[b][rank] = tid;
    } else if (tid < KPAD) {
        sxs[tid] = FLT_MAX;
        g_sxs[b][tid] = FLT_MAX;       // pad tail with +inf
    }
    __syncthreads();
    // first-of-duplicate-run table: sfr[i] = smallest j with sxs[j]==sxs[i]
    if (tid < RK) {
        float x = sxs[tid];
        int j = tid;
        while (j > 0 && sxs[j - 1] == x) --j;   // runs ~always length 1 (random data)
        g_sfr[b][tid] = j;
    }
}

// ---------------------------------------------------------------------------
// Kernel 2: NN searches + partial (sum, sumsq); last CTA finishes the loss.
// Launched with programmatic stream serialization: prologue overlaps stage.
// ---------------------------------------------------------------------------
__global__ void __launch_bounds__(NTH, 1)
nn_kernel(const float* __restrict__ pointx, float* __restrict__ out)
{
    const int split = blockIdx.x;        // 0..SPLIT-1
    const int b     = blockIdx.y;        // 0..RB-1
    const int tid   = threadIdx.x;

    __shared__ float sxs[KPAD];
    __shared__ float sdv[RK];
    __shared__ int   sks[RK];
    __shared__ int   sfr[RK];
    __shared__ double wsum[NTH / 32];
    __shared__ double wsq[NTH / 32];
    __shared__ bool  s_last;

    // ---- Stage-independent prologue (overlaps upstream kernel under PDL) ----
    const int p0 = split * PCHUNK + tid;     // PCHUNK = NTH*PBATCH
    float px[PBATCH];
    #pragma unroll
    for (int u = 0; u < PBATCH; u++)
        px[u] = __ldg(&pointx[p0 + u * NTH]);  // input array: not written by stage

    // Wait for the staged tables to be complete and visible.
    cudaGridDependencySynchronize();

    // Load this row's tables (L2-resident: ~220 KB of unique bytes)
    if (tid < KPAD) sxs[tid] = g_sxs[b][tid];
    if (tid < RK) {
        sdv[tid] = g_sdv[b][tid];
        sks[tid] = g_sks[b][tid];
        sfr[tid] = g_sfr[b][tid];
    }
    __syncthreads();

    // PBATCH independent searches in flight per thread -> PBATCH independent
    // LDS per chain level, amortizing the 29-cycle LDS latency.
    double sum = 0.0, sumsq = 0.0;
    {
        int lo[PBATCH], hi[PBATCH];
        #pragma unroll
        for (int u = 0; u < PBATCH; u++) { lo[u] = 0; hi[u] = KPAD; }
        // lower_bound: first index with sxs[idx] >= px.
        // In-bounds proof: lo advances past mid only when sxs[mid] < px,
        // impossible for pad entries (FLT_MAX), so lo <= RK < KPAD and
        // mid <= 127 always; the lo==hi fixed point is stable.
        #pragma unroll
        for (int it = 0; it < 8; it++) {
            #pragma unroll
            for (int u = 0; u < PBATCH; u++) {
                int mid = (lo[u] + hi[u]) >> 1;
                bool lt = sxs[mid] < px[u];
                lo[u] = lt ? (mid + 1) : lo[u];
                hi[u] = lt ? hi[u] : mid;
            }
        }
        #pragma unroll
        for (int u = 0; u < PBATCH; u++) {
            const int p = p0 + u * NTH;
            const int l = lo[u];
            int chosen;
            if (l == 0) {
                chosen = 0;                      // all x >= px; index 0 is first of its run (min k)
            } else if (l >= RK) {
                chosen = sfr[RK - 1];            // all x < px; first of last duplicate run
            } else {
                int j = sfr[l - 1];              // predecessor run head (min original k in run)
                float dp = fabsf(px[u] - sxs[j]);
                float ds = fabsf(px[u] - sxs[l]);
                if (ds < dp)       chosen = l;
                else if (dp < ds)  chosen = j;
                else               chosen = (sks[j] < sks[l]) ? j : l;  // tie: min original k
            }
            if (p != 0) {                        // losses = var(diff[:, 1:])
                float dv = sdv[chosen];
                sum   += (double)dv;
                sumsq += (double)dv * (double)dv;
            }
        }
    }

    // block reduce (deterministic)
    for (int o = 16; o > 0; o >>= 1) {
        sum   += __shfl_down_sync(0xffffffffu, sum, o);
        sumsq += __shfl_down_sync(0xffffffffu, sumsq, o);
    }
    if ((tid & 31) == 0) {
        wsum[tid >> 5] = sum;
        wsq[tid >> 5]  = sumsq;
    }
    __syncthreads();
    if (tid == 0) {
        double S = 0.0, Q = 0.0;
        #pragma unroll
        for (int w = 0; w < NTH / 32; w++) { S += wsum[w]; Q += wsq[w]; }
        g_part_sum[b * SPLIT + split] = S;
        g_part_sq [b * SPLIT + split] = Q;
        __threadfence();                          // publish partials
        unsigned int t = atomicAdd(&g_ticket, 1u);
        s_last = (t == NBLOCKS - 1);
    }
    __syncthreads();

    // ---- Fused epilogue: the last CTA computes the final loss ----
    if (s_last) {
        __threadfence();                          // acquire all partials
        __shared__ double ws[NTH / 32];
        double v = 0.0;
        if (tid < RB) {                           // one thread per row
            double S = 0.0, Q = 0.0;
            #pragma unroll
            for (int s = 0; s < SPLIT; s++) {     // fixed order: deterministic
                S += g_part_sum[tid * SPLIT + s];
                Q += g_part_sq [tid * SPLIT + s];
            }
            const double M = (double)(RP - 1);
            double mean = S / M;
            v = Q / M - mean * mean;              // jnp.var (ddof=0)
        }
        for (int o = 16; o > 0; o >>= 1)
            v += __shfl_down_sync(0xffffffffu, v, o);
        if ((tid & 31) == 0) ws[tid >> 5] = v;
        __syncthreads();
        if (tid == 0) {
            double s = 0.0;
            #pragma unroll
            for (int w = 0; w < NTH / 32; w++) s += ws[w];
            out[0] = (float)(s / (double)RB);
            g_ticket = 0;                         // reset for next graph replay
        }
    }
}

extern "C" void kernel_launch(void* const* d_in, const int* in_sizes, int n_in,
                              void* d_out, int out_size)
{
    const float* preds  = (const float*)d_in[0];
    const float* target = (const float*)d_in[1];
    const float* Xffp   = (const float*)d_in[2];
    const float* amp    = (const float*)d_in[3];
    const float* pointx = (const float*)d_in[4];
    float* out = (float*)d_out;

    stage_kernel<<<RB, STH>>>(preds, target, Xffp, amp);

    // NN kernel with programmatic dependent launch (prologue overlap).
    dim3 grid(SPLIT, RB);
    cudaLaunchConfig_t cfg = {};
    cfg.gridDim  = grid;
    cfg.blockDim = dim3(NTH, 1, 1);
    cfg.dynamicSmemBytes = 0;
    cfg.stream = 0;                               // same captured default stream
    cudaLaunchAttribute attr[1];
    attr[0].id = cudaLaunchAttributeProgrammaticStreamSerialization;
    attr[0].val.programmaticStreamSerializationAllowed = 1;
    cfg.attrs = attr;
    cfg.numAttrs = 1;
    cudaError_t e = cudaLaunchKernelEx(&cfg, nn_kernel, pointx, out);
    if (e != cudaSuccess) {
        // Fallback: plain dependent launch (GridDependencySynchronize is a
        // no-op without PDL), same results.
        nn_kernel<<<grid, NTH>>>(pointx, out);
    }
}

// round 10
// speedup vs baseline: 1.2951x; 1.2951x over previous
#include <cuda_runtime.h>
#include <cfloat>

// Problem constants (fixed by reference: B=128, N=4096, P=4096, K=100)
constexpr int RB = 128;
constexpr int RN = 4096;
constexpr int RP = 4096;
constexpr int RK = 100;
constexpr int KPAD = 128;      // padded sorted-array size (power of two)
constexpr int TH  = 256;       // threads per CTA
constexpr int NW  = TH / 32;   // warps per CTA
constexpr int PRE = 512;       // prefix/suffix probe length for sign scans
constexpr int OUTER = 4;       // point groups; each thread: 4 consecutive pts/group
static_assert(OUTER * TH * 4 == RP, "point coverage");

__device__ double g_row_var[RB];
__device__ unsigned int g_ticket;   // zero-initialized; reset by last CTA each run

__global__ void __launch_bounds__(TH, 1)
fused_kernel(const float* __restrict__ preds,
             const float* __restrict__ target,
             const float* __restrict__ Xffp,
             const float* __restrict__ amp,
             const float* __restrict__ pointx,
             float* __restrict__ out)
{
    const int b    = blockIdx.x;
    const int tid  = threadIdx.x;
    const int lane = tid & 31;
    const int wid  = tid >> 5;
    const float* trow = target + (size_t)b * RN;

    __shared__ int    w_min[NW];
    __shared__ int    w_max[NW];
    __shared__ int    s_shift;
    __shared__ float  rx[RK];       // gathered X100 (unsorted)
    __shared__ float  rd[RK];       // gathered dvals (unsorted)
    __shared__ float  sxs[KPAD];    // sorted x, padded with +inf
    __shared__ float  sdv[RK];      // dvals in sorted order
    __shared__ int    sks[RK];      // original k in sorted order
    __shared__ int    sfr[RK];      // first index of duplicate run
    __shared__ double ws[NW];
    __shared__ double wq[NW];
    __shared__ bool   s_last;

    // ---- Preload this thread's 16 points (latency hides under Phase A/B) ----
    // Group o covers points [o*1024, o*1024+1024); thread handles 4 consecutive
    // points o*1024 + tid*4 + {0..3} loaded as one float4.
    float4 pxv[OUTER];
    {
        const float4* px4 = reinterpret_cast<const float4*>(pointx);
        #pragma unroll
        for (int o = 0; o < OUTER; o++)
            pxv[o] = px4[o * TH + tid];
    }

    // ---- Phase A: sign scans over target row ----
    // normal_u = target/amp with amp in [0.5,1.5] > 0, so:
    //   normal_u >= 0  <=>  target >= 0     (j_left = first such index)
    //   normal_u <= 0  <=>  target <= 0     (m_right via last such index)
    // Probe a 512-element prefix (resp. suffix); "no hit in probe" is exactly
    // the condition under which farther indices matter, so the rare full-row
    // fallback keeps this exact.
    int mn = RN;   // min index with target[n] >= 0
    int mx = -1;   // max index with target[n] <= 0
    {
        const float4* t4 = reinterpret_cast<const float4*>(trow);
        #pragma unroll
        for (int i = tid; i < PRE / 4; i += TH) {    // prefix probe
            float4 v = t4[i];
            int base = i * 4;
            if (v.x >= 0.f) mn = min(mn, base + 0);
            if (v.y >= 0.f) mn = min(mn, base + 1);
            if (v.z >= 0.f) mn = min(mn, base + 2);
            if (v.w >= 0.f) mn = min(mn, base + 3);
        }
        #pragma unroll
        for (int i = tid; i < PRE / 4; i += TH) {    // suffix probe
            int i4 = (RN - PRE) / 4 + i;
            float4 v = t4[i4];
            int base = i4 * 4;
            if (v.x <= 0.f) mx = max(mx, base + 0);
            if (v.y <= 0.f) mx = max(mx, base + 1);
            if (v.z <= 0.f) mx = max(mx, base + 2);
            if (v.w <= 0.f) mx = max(mx, base + 3);
        }
    }
    // warp redux (single REDUX.MIN/MAX each) + one smem round
    mn = __reduce_min_sync(0xffffffffu, mn);
    mx = __reduce_max_sync(0xffffffffu, mx);
    if (lane == 0) { w_min[wid] = mn; w_max[wid] = mx; }
    __syncthreads();
    {
        int vmn = (lane < NW) ? w_min[lane] : RN;
        int vmx = (lane < NW) ? w_max[lane] : -1;
        vmn = __reduce_min_sync(0xffffffffu, vmn);
        vmx = __reduce_max_sync(0xffffffffu, vmx);
        if (tid == 0) { w_min[0] = vmn; w_max[0] = vmx; }
    }
    __syncthreads();
    // Rare fallback: probe was sign-pure -> full-row scan (exact).
    if (w_min[0] == RN || w_max[0] == -1) {
        const bool need_mn = (w_min[0] == RN);
        const bool need_mx = (w_max[0] == -1);
        mn = RN; mx = -1;
        const float4* t4 = reinterpret_cast<const float4*>(trow);
        for (int i = tid; i < RN / 4; i += TH) {
            float4 v = t4[i];
            int base = i * 4;
            if (need_mn) {
                if (v.x >= 0.f) mn = min(mn, base + 0);
                if (v.y >= 0.f) mn = min(mn, base + 1);
                if (v.z >= 0.f) mn = min(mn, base + 2);
                if (v.w >= 0.f) mn = min(mn, base + 3);
            }
            if (need_mx) {
                if (v.x <= 0.f) mx = max(mx, base + 0);
                if (v.y <= 0.f) mx = max(mx, base + 1);
                if (v.z <= 0.f) mx = max(mx, base + 2);
                if (v.w <= 0.f) mx = max(mx, base + 3);
            }
        }
        mn = __reduce_min_sync(0xffffffffu, mn);
        mx = __reduce_max_sync(0xffffffffu, mx);
        __syncthreads();
        if (lane == 0) {
            if (need_mn) w_min[wid] = mn;
            if (need_mx) w_max[wid] = mx;
        }
        __syncthreads();
        {
            int vmn = (lane < NW) ? w_min[lane] : RN;
            int vmx = (lane < NW) ? w_max[lane] : -1;
            vmn = __reduce_min_sync(0xffffffffu, vmn);
            vmx = __reduce_max_sync(0xffffffffu, vmx);
            if (tid == 0) { w_min[0] = vmn; w_max[0] = vmx; }
        }
        __syncthreads();
    }
    if (tid == 0) {
        int jl = w_min[0];
        if (jl == RN) jl = 0;           // argmax of all-False -> 0
        int k_left = jl + 1;
        int mxi = w_max[0];
        int m_right = (mxi < 0) ? 0 : (RN - 1 - mxi);
        float first = trow[0];
        float last  = trow[RN - 1];
        bool left_case = (last < 0.f) && (first < 0.f);
        s_shift = left_case ? -k_left : m_right;
    }
    if (tid >= RK && tid < KPAD) sxs[tid] = FLT_MAX;   // pad tail with +inf
    __syncthreads();

    // ---- Phase B: gather first K shifted elements, stable rank-sort ----
    if (tid < RK) {
        int i = tid - s_shift;
        i %= RN;
        if (i < 0) i += RN;
        size_t g = (size_t)b * RN + i;
        float a = amp[g];
        rx[tid] = Xffp[g];
        rd[tid] = target[g] / a - preds[g] / a;   // nu_s - nui_s, literal order
    }
    __syncthreads();
    if (tid < RK) {
        float x = rx[tid];
        int rank = 0;
        #pragma unroll 4
        for (int j = 0; j < RK; j++) {
            float xj = rx[j];
            rank += (xj < x) || (xj == x && j < tid);  // stable: ties by original index
        }
        sxs[rank] = x;
        sdv[rank] = rd[tid];
        sks[rank] = tid;
    }
    __syncthreads();
    // first-of-duplicate-run table: sfr[i] = smallest j with sxs[j]==sxs[i]
    if (tid < RK) {
        float x = sxs[tid];
        int j = tid;
        while (j > 0 && sxs[j - 1] == x) --j;   // runs ~always length 1 (random data)
        sfr[tid] = j;
    }
    __syncthreads();

    // ---- Phase C: nearest-neighbor for all 4096 points + variance accum ----
    // 4 independent searches in flight per group -> 4 independent LDS per
    // chain level, amortizing the 29-cycle LDS latency.
    double sum = 0.0, sumsq = 0.0;
    #pragma unroll
    for (int o = 0; o < OUTER; o++) {
        float px[4] = { pxv[o].x, pxv[o].y, pxv[o].z, pxv[o].w };
        int lo[4] = {0, 0, 0, 0};
        int hi[4] = {KPAD, KPAD, KPAD, KPAD};
        // lower_bound: first index with sxs[idx] >= px.
        // In-bounds proof: lo advances past mid only when sxs[mid] < px,
        // impossible for pad entries (FLT_MAX), so lo <= RK < KPAD and
        // mid <= 127 always; the lo==hi fixed point is stable.
        #pragma unroll
        for (int it = 0; it < 8; it++) {
            #pragma unroll
            for (int u = 0; u < 4; u++) {
                int mid = (lo[u] + hi[u]) >> 1;
                bool lt = sxs[mid] < px[u];
                lo[u] = lt ? (mid + 1) : lo[u];
                hi[u] = lt ? hi[u] : mid;
            }
        }
        #pragma unroll
        for (int u = 0; u < 4; u++) {
            const int p = o * (TH * 4) + tid * 4 + u;
            const int l = lo[u];
            int chosen;
            if (l == 0) {
                chosen = 0;                      // all x >= px; index 0 is first of its run (min k)
            } else if (l >= RK) {
                chosen = sfr[RK - 1];            // all x < px; first of last duplicate run
            } else {
                int j = sfr[l - 1];              // predecessor run head (min original k in run)
                float dp = fabsf(px[u] - sxs[j]);
                float ds = fabsf(px[u] - sxs[l]);
                if (ds < dp)       chosen = l;
                else if (dp < ds)  chosen = j;
                else               chosen = (sks[j] < sks[l]) ? j : l;  // tie: min original k
            }
            if (p != 0) {                        // losses = var(diff[:, 1:])
                float dv = sdv[chosen];
                sum   += (double)dv;
                sumsq += (double)dv * (double)dv;
            }
        }
    }

    // ---- Deterministic block reduce -> per-row variance ----
    for (int o = 16; o > 0; o >>= 1) {
        sum   += __shfl_down_sync(0xffffffffu, sum, o);
        sumsq += __shfl_down_sync(0xffffffffu, sumsq, o);
    }
    if (lane == 0) { ws[wid] = sum; wq[wid] = sumsq; }
    __syncthreads();
    if (tid == 0) {
        double S = 0.0, Q = 0.0;
        #pragma unroll
        for (int w = 0; w < NW; w++) { S += ws[w]; Q += wq[w]; }
        const double M = (double)(RP - 1);
        double mean = S / M;
        g_row_var[b] = Q / M - mean * mean;       // jnp.var (ddof=0)
        __threadfence();                          // publish row var
        unsigned int t = atomicAdd(&g_ticket, 1u);
        s_last = (t == RB - 1);
    }
    __syncthreads();

    // ---- Fused epilogue: last CTA averages the 128 row variances ----
    if (s_last) {
        __threadfence();                          // acquire all row vars
        double v = (tid < RB) ? g_row_var[tid] : 0.0;
        for (int o = 16; o > 0; o >>= 1)
            v += __shfl_down_sync(0xffffffffu, v, o);
        if (lane == 0) ws[wid] = v;               // reuse ws (post-sync)
        __syncthreads();
        if (tid == 0) {
            double s = 0.0;
            #pragma unroll
            for (int w = 0; w < NW; w++) s += ws[w];
            out[0] = (float)(s / (double)RB);
            g_ticket = 0;                         // reset for next graph replay
        }
    }
}

extern "C" void kernel_launch(void* const* d_in, const int* in_sizes, int n_in,
                              void* d_out, int out_size)
{
    const float* preds  = (const float*)d_in[0];
    const float* target = (const float*)d_in[1];
    const float* Xffp   = (const float*)d_in[2];
    const float* amp    = (const float*)d_in[3];
    const float* pointx = (const float*)d_in[4];
    float* out = (float*)d_out;

    fused_kernel<<<RB, TH>>>(preds, target, Xffp, amp, pointx, out);
}